// round 2
// baseline (speedup 1.0000x reference)
#include <cuda_runtime.h>
#include <math.h>

// Problem constants
#define NSEQ 512       // B*S
#define BHD 384        // BH
#define NHD 8          // heads
#define HDD 48         // head dim
#define TTOT 16        // T = P + S_C
#define PPRE 4         // P
#define SCDEC 12       // S_C
#define LLAY 4         // L
#define VOC 258
#define HIN 1024
#define FFD 1536
#define EOS_ID 257
#define SCALE_F 0.14433756729740643f   // 1/sqrt(48)

// ---------------- scratch (device globals; no runtime allocation) ----------------
__device__ float g_xout[NSEQ * TTOT * BHD];            // (N,16,384)
__device__ float g_kc[LLAY][NSEQ * TTOT * BHD];        // (N,16,8,48) per layer
__device__ float g_vc[LLAY][NSEQ * TTOT * BHD];
__device__ float g_xi[NSEQ * 4 * BHD];                 // working x (max M=2048 rows)
__device__ float g_h[NSEQ * 4 * BHD];                  // rms output
__device__ float g_qkv[NSEQ * 4 * 3 * BHD];            // (M,1152)
__device__ float g_o[NSEQ * 4 * BHD];                  // attention output
__device__ float g_t[NSEQ * 4 * FFD];                  // ffn intermediate / lm input reuse
__device__ float g_part[8 * NSEQ * BHD];               // split-K partials
__device__ float g_wqkv[LLAY * BHD * 3 * BHD];         // concatenated QKV weights
__device__ int   g_fin[NSEQ];

// ---------------- GEMM: C[M,N] (+)= A[M,K] @ B[K,N], fp32 SIMT ----------------
// Requirements used here: M % 64 == 0, K % (gridDim.z*16) == 0. N guarded.
#define BM 64
#define BN 64
#define BKK 16

template<bool ACC, bool GELU>
__global__ __launch_bounds__(256) void gemm_k(
    const float* __restrict__ A, int lda,
    const float* __restrict__ B, int ldb,
    float* __restrict__ C, int ldc,
    int M, int N, int K)
{
    __shared__ float As[BKK][BM + 4];
    __shared__ float Bs[BKK][BN + 4];
    const int tid = threadIdx.x;
    const int tx = tid & 15;
    const int ty = tid >> 4;
    const int m0 = blockIdx.y * BM;
    const int n0 = blockIdx.x * BN;

    const int Kc   = K / gridDim.z;
    const int kbeg = blockIdx.z * Kc;
    if (gridDim.z > 1) C += (size_t)blockIdx.z * (size_t)M * (size_t)ldc;

    const int aRow = tid >> 4;   // 0..15
    const int aCol = tid & 15;   // 0..15
    const int bRow = tid >> 6;   // 0..3
    const int bCol = tid & 63;   // 0..63

    float acc[4][4];
    #pragma unroll
    for (int r = 0; r < 4; r++)
        #pragma unroll
        for (int c = 0; c < 4; c++) acc[r][c] = 0.f;

    for (int k0 = kbeg; k0 < kbeg + Kc; k0 += BKK) {
        #pragma unroll
        for (int r = 0; r < 4; r++) {
            int row = aRow + r * 16;
            As[aCol][row] = A[(size_t)(m0 + row) * lda + (k0 + aCol)];
        }
        #pragma unroll
        for (int r = 0; r < 4; r++) {
            int krow = bRow + r * 4;
            int col  = n0 + bCol;
            Bs[krow][bCol] = (col < N) ? B[(size_t)(k0 + krow) * ldb + col] : 0.f;
        }
        __syncthreads();
        #pragma unroll
        for (int kk = 0; kk < BKK; kk++) {
            float a[4], b[4];
            #pragma unroll
            for (int r = 0; r < 4; r++) a[r] = As[kk][ty * 4 + r];
            #pragma unroll
            for (int c = 0; c < 4; c++) b[c] = Bs[kk][tx * 4 + c];
            #pragma unroll
            for (int r = 0; r < 4; r++)
                #pragma unroll
                for (int c = 0; c < 4; c++)
                    acc[r][c] += a[r] * b[c];
        }
        __syncthreads();
    }

    #pragma unroll
    for (int r = 0; r < 4; r++) {
        int gr = m0 + ty * 4 + r;
        #pragma unroll
        for (int c = 0; c < 4; c++) {
            int gc = n0 + tx * 4 + c;
            if (gc < N) {
                float v = acc[r][c];
                if (GELU) v = 0.5f * v * (1.f + erff(v * 0.70710678118654752f));
                size_t off = (size_t)gr * (size_t)ldc + gc;
                if (ACC) C[off] += v; else C[off] = v;
            }
        }
    }
}

// ---------------- small helper kernels ----------------

__global__ void init_fin_k() {
    int i = blockIdx.x * blockDim.x + threadIdx.x;
    if (i < NSEQ) g_fin[i] = 0;
}

__global__ void concat_k(const float* __restrict__ Wq,
                         const float* __restrict__ Wk,
                         const float* __restrict__ Wv) {
    int idx = blockIdx.x * blockDim.x + threadIdx.x;
    const int per = BHD * 3 * BHD;          // 442368
    if (idx >= LLAY * per) return;
    int l = idx / per;
    int r = idx - l * per;
    int k = r / (3 * BHD);
    int j = r - k * (3 * BHD);
    float v;
    int base = l * BHD * BHD + k * BHD;
    if (j < BHD)            v = Wq[base + j];
    else if (j < 2 * BHD)   v = Wk[base + j - BHD];
    else                    v = Wv[base + j - 2 * BHD];
    g_wqkv[idx] = v;
}

// RMS norm: one block per row (128 threads), 384 cols
__global__ void rms_k(const float* __restrict__ in, const float* __restrict__ gain,
                      float* __restrict__ out) {
    int row = blockIdx.x;
    int t = threadIdx.x;
    const float* r = in + (size_t)row * BHD;
    float s = 0.f;
    for (int c = t; c < BHD; c += 128) { float v = r[c]; s += v * v; }
    // reduce
    for (int o = 16; o > 0; o >>= 1) s += __shfl_xor_sync(0xffffffffu, s, o);
    __shared__ float sh[4];
    if ((t & 31) == 0) sh[t >> 5] = s;
    __syncthreads();
    __shared__ float sc;
    if (t == 0) {
        float tot = sh[0] + sh[1] + sh[2] + sh[3];
        sc = rsqrtf(tot / (float)BHD + 1e-5f);
    }
    __syncthreads();
    float scale = sc;
    float* w = out + (size_t)row * BHD;
    for (int c = t; c < BHD; c += 128) w[c] = r[c] * scale * gain[c];
}

// copy xi from x_out: rows m = n*Lq+qi, src position srcT+qi
__global__ void copy_xi_k(int Lq, int srcT, int total) {
    int idx = blockIdx.x * blockDim.x + threadIdx.x;
    if (idx >= total) return;
    int m = idx / BHD;
    int c = idx - m * BHD;
    int n = m / Lq;
    int qi = m - n * Lq;
    g_xi[idx] = g_xout[(size_t)n * TTOT * BHD + (size_t)(srcT + qi) * BHD + c];
}

// scatter K,V from qkv buffer into caches
__global__ void scatter_k(int l, int Lq, int pos) {
    int m = blockIdx.x;
    int c = threadIdx.x;      // 384
    int n = m / Lq;
    int qi = m - n * Lq;
    int tpos = pos + qi;
    size_t src = (size_t)m * (3 * BHD);
    size_t dst = ((size_t)n * TTOT + tpos) * BHD + c;
    g_kc[l][dst] = g_qkv[src + BHD + c];
    g_vc[l][dst] = g_qkv[src + 2 * BHD + c];
}

// attention: one block per sequence, 8 warps; warp handles (qi,head) pairs
__global__ void attn_k(int l, int Lq, int pos, int causal) {
    int n = blockIdx.x;
    int warp = threadIdx.x >> 5;
    int lane = threadIdx.x & 31;
    int nk = pos + Lq;
    int npairs = NHD * Lq;
    __shared__ float ps[8][16];
    const float* kc = g_kc[l] + (size_t)n * TTOT * BHD;
    const float* vc = g_vc[l] + (size_t)n * TTOT * BHD;
    for (int pair = warp; pair < npairs; pair += 8) {
        int qi = pair >> 3;
        int hh = pair & 7;
        int m = n * Lq + qi;
        const float* q = g_qkv + (size_t)m * (3 * BHD) + hh * HDD;
        float s = -3.402823466e38f;
        if (lane < nk) {
            const float* kr = kc + (size_t)lane * BHD + hh * HDD;
            float acc = 0.f;
            #pragma unroll
            for (int d = 0; d < HDD; d++) acc += q[d] * kr[d];
            s = acc * SCALE_F;
            if (causal && lane > pos + qi) s = -1e30f;
        }
        float mx = s;
        #pragma unroll
        for (int o = 16; o > 0; o >>= 1) mx = fmaxf(mx, __shfl_xor_sync(0xffffffffu, mx, o));
        float e = (lane < nk) ? expf(s - mx) : 0.f;
        float den = e;
        #pragma unroll
        for (int o = 16; o > 0; o >>= 1) den += __shfl_xor_sync(0xffffffffu, den, o);
        float p = e / den;
        if (lane < 16) ps[warp][lane] = (lane < nk) ? p : 0.f;
        __syncwarp();
        float* op = g_o + (size_t)m * BHD + hh * HDD;
        float o1 = 0.f, o2 = 0.f;
        for (int t2 = 0; t2 < nk; t2++) {
            float pt = ps[warp][t2];
            const float* vr = vc + (size_t)t2 * BHD + hh * HDD;
            o1 += pt * vr[lane];
            if (lane < 16) o2 += pt * vr[32 + lane];
        }
        op[lane] = o1;
        if (lane < 16) op[32 + lane] = o2;
        __syncwarp();
    }
}

// xi += sum of split-K partials
__global__ void reduce_k(int ks, int total) {
    int idx = blockIdx.x * blockDim.x + threadIdx.x;
    if (idx >= total) return;
    float s = 0.f;
    for (int z = 0; z < ks; z++) s += g_part[(size_t)z * total + idx];
    g_xi[idx] += s;
}

// gen = xi[:, -1]; argmax / EOS / finished logic; write x_out[:, 4+step]
__global__ void gen_k(int Lq, int step) {
    int n = blockIdx.x;
    int t = threadIdx.x;   // 128
    const float* gen = g_xi + (size_t)(n * Lq + Lq - 1) * BHD;
    float bv = -3.402823466e38f;
    int bi = 0;
    for (int c = t; c < BHD; c += 128) {
        float v = gen[c];
        if (v > bv) { bv = v; bi = c; }
    }
    __shared__ float sv[128];
    __shared__ int si[128];
    sv[t] = bv; si[t] = bi;
    __syncthreads();
    for (int s = 64; s > 0; s >>= 1) {
        if (t < s) {
            if (sv[t + s] > sv[t] || (sv[t + s] == sv[t] && si[t + s] < si[t])) {
                sv[t] = sv[t + s]; si[t] = si[t + s];
            }
        }
        __syncthreads();
    }
    __shared__ int unf_s;
    if (t == 0) {
        int fin = g_fin[n];
        unf_s = !fin;
        if (!fin && si[0] == EOS_ID) g_fin[n] = 1;
    }
    __syncthreads();
    int unf = unf_s;
    float* dst = g_xout + (size_t)n * TTOT * BHD + (size_t)(PPRE + step) * BHD;
    for (int c = t; c < BHD; c += 128) dst[c] = unf ? gen[c] : 0.f;
}

// compact x_out[:, P:] into dense (6144,384) in g_t for the LM head
__global__ void compact_k() {
    int m = blockIdx.x;       // 6144
    int c = threadIdx.x;      // 384
    int n = m / SCDEC;
    int tt = m - n * SCDEC;
    g_t[(size_t)m * BHD + c] = g_xout[(size_t)n * TTOT * BHD + (size_t)(PPRE + tt) * BHD + c];
}

// ---------------- driver ----------------
extern "C" void kernel_launch(void* const* d_in, const int* in_sizes, int n_in,
                              void* d_out, int out_size) {
    (void)in_sizes; (void)n_in; (void)out_size;
    const float* x     = (const float*)d_in[0];
    const float* Wproj = (const float*)d_in[2];
    const float* an    = (const float*)d_in[3];
    const float* Wq    = (const float*)d_in[4];
    const float* Wk    = (const float*)d_in[5];
    const float* Wv    = (const float*)d_in[6];
    const float* Wo    = (const float*)d_in[7];
    const float* fn    = (const float*)d_in[8];
    const float* W1    = (const float*)d_in[9];
    const float* W2    = (const float*)d_in[10];
    const float* Wlm   = (const float*)d_in[11];
    float* out = (float*)d_out;

    float *p_xout, *p_xi, *p_h, *p_qkv, *p_o, *p_t, *p_part, *p_wqkv;
    cudaGetSymbolAddress((void**)&p_xout, g_xout);
    cudaGetSymbolAddress((void**)&p_xi,   g_xi);
    cudaGetSymbolAddress((void**)&p_h,    g_h);
    cudaGetSymbolAddress((void**)&p_qkv,  g_qkv);
    cudaGetSymbolAddress((void**)&p_o,    g_o);
    cudaGetSymbolAddress((void**)&p_t,    g_t);
    cudaGetSymbolAddress((void**)&p_part, g_part);
    cudaGetSymbolAddress((void**)&p_wqkv, g_wqkv);

    init_fin_k<<<2, 256>>>();
    concat_k<<<(LLAY * BHD * 3 * BHD + 255) / 256, 256>>>(Wq, Wk, Wv);

    // Input projection: (512,1024)@(1024,1536) -> x_out[:, :4, :] (ldc=6144)
    gemm_k<false, false><<<dim3(FFD / BN, NSEQ / BM, 1), 256>>>(
        x, HIN, Wproj, FFD, p_xout, TTOT * BHD, NSEQ, FFD, HIN);

    for (int i = 0; i < SCDEC; i++) {
        const int Lq = (i == 0) ? PPRE : 1;
        const int pos = (i == 0) ? 0 : (PPRE + i - 1);
        const int Mrows = NSEQ * Lq;
        const int causal = (i == 0) ? 1 : 0;
        const int total = Mrows * BHD;

        copy_xi_k<<<(total + 255) / 256, 256>>>(Lq, pos, total);

        for (int l = 0; l < LLAY; l++) {
            // attn rms
            rms_k<<<Mrows, 128>>>(p_xi, an + l * BHD, p_h);
            // fused QKV GEMM: (M,384)@(384,1152)
            gemm_k<false, false><<<dim3(3 * BHD / BN, Mrows / BM, 1), 256>>>(
                p_h, BHD, p_wqkv + (size_t)l * BHD * 3 * BHD, 3 * BHD,
                p_qkv, 3 * BHD, Mrows, 3 * BHD, BHD);
            // write K,V into caches
            scatter_k<<<Mrows, BHD>>>(l, Lq, pos);
            // attention
            attn_k<<<NSEQ, 256>>>(l, Lq, pos, causal);
            // o-projection, accumulate into xi
            if (i == 0) {
                gemm_k<true, false><<<dim3(BHD / BN, Mrows / BM, 1), 256>>>(
                    p_o, BHD, Wo + (size_t)l * BHD * BHD, BHD,
                    p_xi, BHD, Mrows, BHD, BHD);
            } else {
                gemm_k<false, false><<<dim3(BHD / BN, Mrows / BM, 4), 256>>>(
                    p_o, BHD, Wo + (size_t)l * BHD * BHD, BHD,
                    p_part, BHD, Mrows, BHD, BHD);
                reduce_k<<<(total + 255) / 256, 256>>>(4, total);
            }
            // ffn rms
            rms_k<<<Mrows, 128>>>(p_xi, fn + l * BHD, p_h);
            // FFN1 + exact GELU epilogue: (M,384)@(384,1536)
            gemm_k<false, true><<<dim3(FFD / BN, Mrows / BM, 1), 256>>>(
                p_h, BHD, W1 + (size_t)l * BHD * FFD, FFD,
                p_t, FFD, Mrows, FFD, BHD);
            // FFN2 accumulate: (M,1536)@(1536,384)
            if (i == 0) {
                gemm_k<true, false><<<dim3(BHD / BN, Mrows / BM, 1), 256>>>(
                    p_t, FFD, W2 + (size_t)l * FFD * BHD, BHD,
                    p_xi, BHD, Mrows, BHD, FFD);
            } else {
                gemm_k<false, false><<<dim3(BHD / BN, Mrows / BM, 8), 256>>>(
                    p_t, FFD, W2 + (size_t)l * FFD * BHD, BHD,
                    p_part, BHD, Mrows, BHD, FFD);
                reduce_k<<<(total + 255) / 256, 256>>>(8, total);
            }
        }
        // gen / EOS / write x_out[:, 4+i]
        gen_k<<<NSEQ, 128>>>(Lq, i);
    }

    // LM head: compact (6144,384), then @(384,258) -> out
    compact_k<<<NSEQ * SCDEC, BHD>>>();
    gemm_k<false, false><<<dim3((VOC + BN - 1) / BN, NSEQ * SCDEC / BM, 1), 256>>>(
        p_t, BHD, Wlm, VOC, out, VOC, NSEQ * SCDEC, VOC, BHD);
}